// round 9
// baseline (speedup 1.0000x reference)
#include <cuda_runtime.h>
#include <cuda_fp16.h>
#include <cstdint>

#define D_DIM 768
#define V_OFF (10240*768)
#define TBM 128
#define TBN 64
#define NSTG 12                  // K stages of 64 halfs
#define ASTG 16384               // 128 rows * 128B
#define BSTG 8192                // 64 rows * 128B
#define POS_OFF (2*(ASTG+BSTG))            // 49152
#define SMEM_TOTAL (POS_OFF + 128*12)      // + sO0/sO1/sPm

__device__ __half g_Bh[D_DIM*D_DIM];     // rn_f16(W), row-major (d, f)
__device__ __half g_Ah[16384*D_DIM];     // rn_f16(2*patch-1), (m, f)

__device__ __forceinline__ uint32_t smem_u32(const void* p){
  uint32_t a;
  asm("{ .reg .u64 t; cvta.to.shared.u64 t, %1; cvt.u32.u64 %0, t; }" : "=r"(a) : "l"(p));
  return a;
}
__device__ __forceinline__ void mma16(float* c, const uint32_t* a, uint32_t b0, uint32_t b1){
  asm volatile(
    "mma.sync.aligned.m16n8k16.row.col.f32.f16.f16.f32 "
    "{%0,%1,%2,%3},{%4,%5,%6,%7},{%8,%9},{%0,%1,%2,%3};\n"
    : "+f"(c[0]), "+f"(c[1]), "+f"(c[2]), "+f"(c[3])
    : "r"(a[0]), "r"(a[1]), "r"(a[2]), "r"(a[3]), "r"(b0), "r"(b1));
}
__device__ __forceinline__ void ldsm4(uint32_t* r, uint32_t addr){
  asm volatile("ldmatrix.sync.aligned.m8n8.x4.shared.b16 {%0,%1,%2,%3}, [%4];"
    : "=r"(r[0]), "=r"(r[1]), "=r"(r[2]), "=r"(r[3]) : "r"(addr));
}
__device__ __forceinline__ void cpasync16(uint32_t dst, const void* src){
  asm volatile("cp.async.cg.shared.global [%0], [%1], 16;"
               :: "r"(dst), "l"(src) : "memory");
}
__device__ __forceinline__ uint32_t pack2(float x, float y){
  __half2 h = __floats2half2_rn(x, y);
  return *reinterpret_cast<uint32_t*>(&h);
}

// ---- prep: fully-coalesced conversion of A (patch-major, 2x-1) and B ----
// A blocks: thread owns one 16B chunk of g_Ah per iter: q = m*96 + j, f = j*8
// B blocks: thread owns one 16B chunk of g_Bh per iter
__global__ void __launch_bounds__(256) prep_ab(const float* __restrict__ pix,
                                               const float* __restrict__ w){
  const int blk = blockIdx.x;
  const int t   = threadIdx.x;
  if (blk < 1536) {
    #pragma unroll
    for (int i = 0; i < 4; i++) {
      const int q = blk*1024 + i*256 + t;
      const int m = q / 96, j = q - m*96;
      const int f = j*8;
      const int b = m >> 10, n = m & 1023;
      const float* src = pix + b*786432 + (f >> 8)*262144
                       + (((n >> 5) << 4) + ((f >> 4) & 15))*512
                       + (n & 31)*16 + (f & 15);
      float4 v0 = *reinterpret_cast<const float4*>(src);
      float4 v1 = *reinterpret_cast<const float4*>(src + 4);
      uint4 u;
      u.x = pack2(fmaf(2.f,v0.x,-1.f), fmaf(2.f,v0.y,-1.f));
      u.y = pack2(fmaf(2.f,v0.z,-1.f), fmaf(2.f,v0.w,-1.f));
      u.z = pack2(fmaf(2.f,v1.x,-1.f), fmaf(2.f,v1.y,-1.f));
      u.w = pack2(fmaf(2.f,v1.z,-1.f), fmaf(2.f,v1.w,-1.f));
      reinterpret_cast<uint4*>(g_Ah)[q] = u;
    }
  } else {
    #pragma unroll
    for (int i = 0; i < 4; i++) {
      const int q = (blk - 1536)*1024 + i*256 + t;
      const float4* s4 = reinterpret_cast<const float4*>(w) + q*2;
      float4 v0 = s4[0], v1 = s4[1];
      uint4 u;
      u.x = pack2(v0.x, v0.y); u.y = pack2(v0.z, v0.w);
      u.z = pack2(v1.x, v1.y); u.w = pack2(v1.z, v1.w);
      reinterpret_cast<uint4*>(g_Bh)[q] = u;
    }
  }
}

// ---- main GEMM + pos-embed: 128x64 tile, 2-stage pipeline, 4 CTAs/SM ----
__global__ void __launch_bounds__(256, 4)
gemma4_patch_embed(const float* __restrict__ ptab,     // (2,10240,768)
                   const int*   __restrict__ pids,     // (16,1024,2)
                   const int*   __restrict__ padp,     // (16,1024) bool-as-i32
                   float* __restrict__ out)            // (16,1024,768)
{
  extern __shared__ char smem[];
  const uint32_t sA = smem_u32(smem);             // 2 x ASTG
  const uint32_t sB = sA + 2*ASTG;                // 2 x BSTG
  int*   sO0 = reinterpret_cast<int*>(smem + POS_OFF);
  int*   sO1 = sO0 + 128;
  float* sPm = reinterpret_cast<float*>(sO1 + 128);
  const int t  = threadIdx.x;
  const int m0 = blockIdx.y * TBM;
  const int n0 = blockIdx.x * TBN;

  // pos-ids into smem once
  if (t < TBM) {
    const int m = m0 + t;
    int x = pids[2*m];     if (x < 0) x = 0;
    int y = pids[2*m + 1]; if (y < 0) y = 0;
    sO0[t] = x * D_DIM;
    sO1[t] = V_OFF + y * D_DIM;
    sPm[t] = (padp[m] != 0) ? 0.f : 1.f;
  }

  // ---- producers ----
  const int rA  = t >> 1;
  const int ubA = (t & 1) * 4;
  const __half* aSrc0 = g_Ah + (size_t)(m0 + rA)*D_DIM + ubA*8;
  uint32_t aDst[4];
  #pragma unroll
  for (int u = 0; u < 4; u++)
    aDst[u] = rA*128 + (((ubA + u) ^ (rA & 7)) << 4);
  const int rB  = t >> 2;
  const int ubB = (t & 3) * 2;
  const __half* bSrc0 = g_Bh + (n0 + rB)*D_DIM + ubB*8;
  uint32_t bDst[2];
  #pragma unroll
  for (int u = 0; u < 2; u++)
    bDst[u] = rB*128 + (((ubB + u) ^ (rB & 7)) << 4);

  auto issueStage = [&](int s){
    const uint32_t aB = sA + (s & 1) * ASTG;
    const uint32_t bB = sB + (s & 1) * BSTG;
    const __half* as = aSrc0 + s*64;
    const __half* bs = bSrc0 + s*64;
    #pragma unroll
    for (int u = 0; u < 4; u++)
      cpasync16(aB + aDst[u], as + u*8);
    #pragma unroll
    for (int u = 0; u < 2; u++)
      cpasync16(bB + bDst[u], bs + u*8);
  };

  // ---- consumer setup: warp grid 4(m) x 2(n); warp tile 32x32 ----
  const int warp = t >> 5, lid = t & 31;
  const int wm = (warp >> 1) * 32;
  const int wn = (warp & 1) * 32;
  const int h16 = lid >> 4;
  const int x7  = lid & 7;
  uint32_t aLM[2], bLM[2];
  #pragma unroll
  for (int tr = 0; tr < 2; tr++)
    aLM[tr] = sA + (wm + tr*16 + (lid & 15))*128;
  #pragma unroll
  for (int ng = 0; ng < 2; ng++)
    bLM[ng] = sB + (wn + ng*16 + (lid & 15))*128;

  float acc[2][4][4];
  #pragma unroll
  for (int i = 0; i < 2; i++)
    #pragma unroll
    for (int j = 0; j < 4; j++)
      #pragma unroll
      for (int k = 0; k < 4; k++) acc[i][j][k] = 0.f;

  issueStage(0);
  asm volatile("cp.async.commit_group;" ::: "memory");

  for (int s = 0; s < NSTG; s++) {
    asm volatile("cp.async.wait_group 0;" ::: "memory");
    __syncthreads();
    if (s + 1 < NSTG) {
      issueStage(s + 1);
      asm volatile("cp.async.commit_group;" ::: "memory");
    }

    const uint32_t aBuf = (s & 1) * ASTG;
    const uint32_t bBuf = (s & 1) * BSTG;
    #pragma unroll
    for (int kk = 0; kk < 4; kk++) {
      const uint32_t cu16 = (uint32_t)(((kk*2 + h16) ^ x7) << 4);
      uint32_t af[2][4], br[2][4];
      #pragma unroll
      for (int tr = 0; tr < 2; tr++) ldsm4(af[tr], aLM[tr] + aBuf + cu16);
      #pragma unroll
      for (int ng = 0; ng < 2; ng++) ldsm4(br[ng], bLM[ng] + bBuf + cu16);
      #pragma unroll
      for (int tm = 0; tm < 2; tm++) {
        mma16(acc[tm][0], af[tm], br[0][0], br[0][2]);
        mma16(acc[tm][1], af[tm], br[0][1], br[0][3]);
        mma16(acc[tm][2], af[tm], br[1][0], br[1][2]);
        mma16(acc[tm][3], af[tm], br[1][1], br[1][3]);
      }
    }
  }

  // ---- epilogue ----
  const int g  = lid >> 2, t4 = lid & 3;
  #pragma unroll
  for (int tm = 0; tm < 2; tm++) {
    #pragma unroll
    for (int half = 0; half < 2; half++) {
      const int lrow = wm + tm*16 + g + half*8;
      const int m = m0 + lrow;
      const int o0 = sO0[lrow];
      const int o1 = sO1[lrow];
      const float pm = sPm[lrow];
      float* orow = out + (size_t)m * D_DIM + n0;
      #pragma unroll
      for (int tn = 0; tn < 4; tn++) {
        const int col = wn + tn*8 + t4*2;
        const int gc  = n0 + col;
        float2 e0 = *reinterpret_cast<const float2*>(ptab + o0 + gc);
        float2 e1 = *reinterpret_cast<const float2*>(ptab + o1 + gc);
        float2 r;
        r.x = acc[tm][tn][half*2 + 0] + pm * (e0.x + e1.x);
        r.y = acc[tm][tn][half*2 + 1] + pm * (e0.y + e1.y);
        *reinterpret_cast<float2*>(orow + col) = r;
      }
    }
  }
}

extern "C" void kernel_launch(void* const* d_in, const int* in_sizes, int n_in,
                              void* d_out, int out_size) {
  const float* pix  = (const float*)d_in[0];
  const float* w    = (const float*)d_in[1];
  const float* tab  = (const float*)d_in[2];
  const int*   pids = (const int*)d_in[3];
  const int*   padp = (const int*)d_in[4];
  float* out = (float*)d_out;

  prep_ab<<<1536 + 72, 256>>>(pix, w);

  static int smemSet = 0;
  if (!smemSet) {
    cudaFuncSetAttribute(gemma4_patch_embed,
                         cudaFuncAttributeMaxDynamicSharedMemorySize, SMEM_TOTAL);
    smemSet = 1;
  }
  dim3 grid(D_DIM / TBN, (16 * 1024) / TBM);   // (12, 128)
  gemma4_patch_embed<<<grid, 256, SMEM_TOTAL>>>(tab, pids, padp, out);
}